// round 1
// baseline (speedup 1.0000x reference)
#include <cuda_runtime.h>
#include <cstdint>
#include <math.h>

// Problem constants (fixed by the reference)
#define NN 100000
#define EE 1600000
#define GG 1000
#define DIN 128
#define DD 300
#define LL 5
#define CC 10

// ---------------- persistent scratch (static device memory; allocation-free) ----
__device__ float g_H   [(size_t)NN*DD];   // current layer h
__device__ float g_HL  [(size_t)NN*DD];   // h + vn[batch]
__device__ float g_AGG [(size_t)NN*DD];   // (1+eps)*hl + sum_neighbors
__device__ float g_HMAX[(size_t)NN*DD];   // JK running max
__device__ float g_T   [(size_t)NN*2*DD]; // hidden 600
__device__ float g_VN  [(size_t)GG*DD];
__device__ float g_VTMP[(size_t)GG*DD];
__device__ float g_U   [(size_t)GG*2*DD];
__device__ float g_GATE[NN];
__device__ float g_E   [NN];
__device__ float g_GMAX[GG];
__device__ float g_ESUM[GG];
__device__ float g_GREP[(size_t)GG*DD];
__device__ int   g_is64_batch;
__device__ int   g_is64_edge;

// ---------------- helpers ----------------
__device__ __forceinline__ unsigned long long ffma2(unsigned long long a,
                                                    unsigned long long b,
                                                    unsigned long long c) {
    unsigned long long d;
    asm("fma.rn.f32x2 %0, %1, %2, %3;" : "=l"(d) : "l"(a), "l"(b), "l"(c));
    return d;
}

union UF2 { unsigned long long u; float2 f; };
__device__ __forceinline__ float2 u2f(unsigned long long v) { UF2 t; t.u = v; return t.f; }

__device__ __forceinline__ void redAdd4(float4* p, float4 v) {
    asm volatile("red.global.add.v4.f32 [%0], {%1,%2,%3,%4};"
                 :: "l"(p), "f"(v.x), "f"(v.y), "f"(v.z), "f"(v.w) : "memory");
}

__device__ __forceinline__ long long ldidx(const void* p, long long i, int is64) {
    return is64 ? ((const long long*)p)[i] : (long long)((const int*)p)[i];
}

__device__ __forceinline__ void atomicMaxFloat(float* addr, float val) {
    int* ia = (int*)addr;
    int old = *ia;
    while (__int_as_float(old) < val) {
        int assumed = old;
        old = atomicCAS(ia, assumed, __float_as_int(val));
        if (old == assumed) break;
    }
}

// Detect whether index buffers are int64 (odd 32-bit words are all zero in a
// window where int32 data would surely be nonzero) or int32.
__global__ void detect_kernel(const void* batch, const void* eidx) {
    const int* b = (const int*)batch;
    int z = 1;
    for (int i = 0; i < 64; i++) if (b[NN/2 + 2*i + 1] != 0) z = 0;
    g_is64_batch = z;
    const int* e = (const int*)eidx;
    int z2 = 1;
    for (int i = 0; i < 64; i++) if (e[2*i + 1] != 0) z2 = 0;
    g_is64_edge = z2;
}

// ---------------- GEMM: C[M,N] = epi(A[M,K] @ B[K,N]) ----------------
// epi: y = (acc + bias[n]) * scale[n] + shift[n]  (scale/shift may be null -> 1/0)
// relu flag; exmode: 0 none, 1 EX=y (copy), 2 EX=max(EX,y)
// Inner loop uses packed f32x2 FMA (FFMA2): 2x fp32 throughput on Blackwell.
#define BM 128
#define BN 64
#define BK 16

__global__ __launch_bounds__(256)
void gemm_kernel(const float* __restrict__ A, const float* __restrict__ B,
                 const float* __restrict__ bias, const float* __restrict__ scale,
                 const float* __restrict__ shift,
                 float* __restrict__ C, float* __restrict__ EX,
                 int M, int K, int N, int relu, int exmode)
{
    __shared__ float As[BK][BM + 4];      // transposed A tile
    __shared__ float Bs[BK][2*BN + 4];    // pairwise-duplicated B tile

    const int tid = threadIdx.x;
    const int tx = tid & 15;              // 16 col-groups of 4 cols
    const int ty = tid >> 4;              // 16 row-groups of 8 rows
    const int m0 = blockIdx.x * BM;
    const int n0 = blockIdx.y * BN;

    unsigned long long acc[4][4];         // [m-pair][n] packed f32x2 accumulators
    #pragma unroll
    for (int i = 0; i < 4; i++)
        #pragma unroll
        for (int j = 0; j < 4; j++) acc[i][j] = 0ull;

    for (int kt = 0; kt < K; kt += BK) {
        // load A tile (2 float4 per thread), store transposed
        #pragma unroll
        for (int i = 0; i < 2; i++) {
            int q = tid + i * 256;
            int row = q >> 2, c4 = q & 3;
            int gr = m0 + row, gk = kt + c4 * 4;
            float4 v = make_float4(0.f, 0.f, 0.f, 0.f);
            if (gr < M && gk + 4 <= K)
                v = *(const float4*)(A + (size_t)gr * K + gk);
            As[c4*4+0][row] = v.x; As[c4*4+1][row] = v.y;
            As[c4*4+2][row] = v.z; As[c4*4+3][row] = v.w;
        }
        // load B tile (1 float4 per thread), store each value duplicated
        {
            int krow = tid >> 4, c4 = tid & 15;
            int gk = kt + krow, gn = n0 + c4 * 4;
            float4 v = make_float4(0.f, 0.f, 0.f, 0.f);
            if (gk < K && gn + 4 <= N)
                v = *(const float4*)(B + (size_t)gk * N + gn);
            float4 d0 = make_float4(v.x, v.x, v.y, v.y);
            float4 d1 = make_float4(v.z, v.z, v.w, v.w);
            *(float4*)&Bs[krow][c4*8]     = d0;
            *(float4*)&Bs[krow][c4*8 + 4] = d1;
        }
        __syncthreads();

        #pragma unroll
        for (int kk = 0; kk < BK; kk++) {
            float4 a0 = *(const float4*)&As[kk][ty*8];
            float4 a1 = *(const float4*)&As[kk][ty*8 + 4];
            float4 b0 = *(const float4*)&Bs[kk][tx*8];
            float4 b1 = *(const float4*)&Bs[kk][tx*8 + 4];
            ulonglong2 A0 = *reinterpret_cast<ulonglong2*>(&a0);
            ulonglong2 A1 = *reinterpret_cast<ulonglong2*>(&a1);
            ulonglong2 B0 = *reinterpret_cast<ulonglong2*>(&b0);
            ulonglong2 B1 = *reinterpret_cast<ulonglong2*>(&b1);
            unsigned long long a2[4] = {A0.x, A0.y, A1.x, A1.y};
            unsigned long long bd[4] = {B0.x, B0.y, B1.x, B1.y};
            #pragma unroll
            for (int mp = 0; mp < 4; mp++) {
                acc[mp][0] = ffma2(a2[mp], bd[0], acc[mp][0]);
                acc[mp][1] = ffma2(a2[mp], bd[1], acc[mp][1]);
                acc[mp][2] = ffma2(a2[mp], bd[2], acc[mp][2]);
                acc[mp][3] = ffma2(a2[mp], bd[3], acc[mp][3]);
            }
        }
        __syncthreads();
    }

    // epilogue
    const int cb = n0 + tx * 4;
    const bool colOK = (cb + 4) <= N;
    float4 b4 = make_float4(0,0,0,0), s4 = make_float4(1,1,1,1), sh4 = make_float4(0,0,0,0);
    if (colOK) {
        b4 = *(const float4*)(bias + cb);
        if (scale) {
            s4  = *(const float4*)(scale + cb);
            sh4 = *(const float4*)(shift + cb);
        }
    }
    #pragma unroll
    for (int mp = 0; mp < 4; mp++) {
        float2 q0 = u2f(acc[mp][0]);
        float2 q1 = u2f(acc[mp][1]);
        float2 q2 = u2f(acc[mp][2]);
        float2 q3 = u2f(acc[mp][3]);
        #pragma unroll
        for (int h = 0; h < 2; h++) {
            int r = m0 + ty * 8 + mp * 2 + h;
            if (r >= M || !colOK) continue;
            float4 y;
            y.x = h ? q0.y : q0.x;
            y.y = h ? q1.y : q1.x;
            y.z = h ? q2.y : q2.x;
            y.w = h ? q3.y : q3.x;
            y.x = (y.x + b4.x) * s4.x + sh4.x;
            y.y = (y.y + b4.y) * s4.y + sh4.y;
            y.z = (y.z + b4.z) * s4.z + sh4.z;
            y.w = (y.w + b4.w) * s4.w + sh4.w;
            if (relu) {
                y.x = fmaxf(y.x, 0.f); y.y = fmaxf(y.y, 0.f);
                y.z = fmaxf(y.z, 0.f); y.w = fmaxf(y.w, 0.f);
            }
            *(float4*)(C + (size_t)r * N + cb) = y;
            if (exmode == 1) {
                *(float4*)(EX + (size_t)r * N + cb) = y;
            } else if (exmode == 2) {
                float4 o = *(float4*)(EX + (size_t)r * N + cb);
                o.x = fmaxf(o.x, y.x); o.y = fmaxf(o.y, y.y);
                o.z = fmaxf(o.z, y.z); o.w = fmaxf(o.w, y.w);
                *(float4*)(EX + (size_t)r * N + cb) = o;
            }
        }
    }
}

// ---------------- per-node / per-edge kernels ----------------
__global__ void init_vn_kernel(const float* __restrict__ vn0) {
    int i = blockIdx.x * blockDim.x + threadIdx.x;
    if (i < GG * DD) {
        float v = vn0[i % DD];
        g_VN[i] = v;
        g_VTMP[i] = v;
    }
}

// HL = H + VN[batch]; AGG = (1+eps_l)*HL; VTMP[batch] += HL (vec4 red)
__global__ void node_pre_kernel(const void* __restrict__ batch,
                                const float* __restrict__ eps, int l, int addVT) {
    int w = (blockIdx.x * blockDim.x + threadIdx.x) >> 5;
    int lane = threadIdx.x & 31;
    if (w >= NN) return;
    int is64 = g_is64_batch;
    long long b = ldidx(batch, w, is64);
    float e1 = 1.0f + __ldg(eps + l);
    const float4* h  = (const float4*)(g_H  + (size_t)w * DD);
    const float4* vn = (const float4*)(g_VN + (size_t)b * DD);
    float4* hl = (float4*)(g_HL  + (size_t)w * DD);
    float4* ag = (float4*)(g_AGG + (size_t)w * DD);
    float4* vt = (float4*)(g_VTMP + (size_t)b * DD);
    for (int c = lane; c < DD/4; c += 32) {
        float4 hv = h[c], vv = vn[c];
        float4 s = make_float4(hv.x+vv.x, hv.y+vv.y, hv.z+vv.z, hv.w+vv.w);
        hl[c] = s;
        ag[c] = make_float4(s.x*e1, s.y*e1, s.z*e1, s.w*e1);
        if (addVT) redAdd4(vt + c, s);
    }
}

// AGG[dst] += HL[src] for every edge; one warp per edge, vec4 REDG
__global__ void edge_kernel(const void* __restrict__ ei) {
    long long w = ((long long)blockIdx.x * blockDim.x + threadIdx.x) >> 5;
    int lane = threadIdx.x & 31;
    if (w >= EE) return;
    int is64 = g_is64_edge;
    long long s = ldidx(ei, w, is64);
    long long d = ldidx(ei, (long long)EE + w, is64);
    const float4* src = (const float4*)(g_HL + (size_t)s * DD);
    float4* dst = (float4*)(g_AGG + (size_t)d * DD);
    #pragma unroll
    for (int c = lane; c < DD/4; c += 32)
        redAdd4(dst + c, __ldg(src + c));
}

__global__ void init_pool_kernel() {
    int i = blockIdx.x * blockDim.x + threadIdx.x;
    if (i < GG) { g_GMAX[i] = __int_as_float(0xff800000); g_ESUM[i] = 0.f; }
    if (i < GG * DD) g_GREP[i] = 0.f;
}

// gate[i] = T[i,:] . gW2 + gb2 ; per-graph running max
__global__ void gate_kernel(const float* __restrict__ gW2, const float* __restrict__ gb2,
                            const void* __restrict__ batch) {
    int w = (blockIdx.x * blockDim.x + threadIdx.x) >> 5;
    int lane = threadIdx.x & 31;
    if (w >= NN) return;
    const float* t = g_T + (size_t)w * (2*DD);
    float s = 0.f;
    for (int c = lane; c < 2*DD; c += 32) s += t[c] * __ldg(gW2 + c);
    #pragma unroll
    for (int o = 16; o > 0; o >>= 1) s += __shfl_xor_sync(0xffffffffu, s, o);
    if (lane == 0) {
        float g = s + __ldg(gb2);
        g_GATE[w] = g;
        long long b = ldidx(batch, w, g_is64_batch);
        atomicMaxFloat(&g_GMAX[b], g);
    }
}

__global__ void exp_kernel(const void* __restrict__ batch) {
    int i = blockIdx.x * blockDim.x + threadIdx.x;
    if (i >= NN) return;
    long long b = ldidx(batch, i, g_is64_batch);
    float e = expf(g_GATE[i] - g_GMAX[b]);
    g_E[i] = e;
    atomicAdd(&g_ESUM[b], e);
}

// GREP[b] += HMAX[i] * (E[i]/ESUM[b])
__global__ void pool_kernel(const void* __restrict__ batch) {
    int w = (blockIdx.x * blockDim.x + threadIdx.x) >> 5;
    int lane = threadIdx.x & 31;
    if (w >= NN) return;
    long long b = ldidx(batch, w, g_is64_batch);
    float wgt = g_E[w] / g_ESUM[b];
    const float4* src = (const float4*)(g_HMAX + (size_t)w * DD);
    float4* dst = (float4*)(g_GREP + (size_t)b * DD);
    #pragma unroll
    for (int c = lane; c < DD/4; c += 32) {
        float4 v = src[c];
        redAdd4(dst + c, make_float4(v.x*wgt, v.y*wgt, v.z*wgt, v.w*wgt));
    }
}

__global__ void out_kernel(const float* __restrict__ pW, const float* __restrict__ pb,
                           float* __restrict__ out) {
    int i = blockIdx.x * blockDim.x + threadIdx.x;
    if (i >= GG * CC) return;
    int g = i / CC, c = i % CC;
    float s = __ldg(pb + c);
    const float* gr = g_GREP + (size_t)g * DD;
    for (int k = 0; k < DD; k++) s += gr[k] * __ldg(pW + k * CC + c);
    out[i] = s;
}

// ---------------- launch ----------------
extern "C" void kernel_launch(void* const* d_in, const int* in_sizes, int n_in,
                              void* d_out, int out_size) {
    const float* x      = (const float*)d_in[0];
    const void*  eidx   = d_in[1];
    const void*  batch  = d_in[2];
    const float* enc_W  = (const float*)d_in[3];
    const float* enc_b  = (const float*)d_in[4];
    const float* eps    = (const float*)d_in[5];
    const float* cW1    = (const float*)d_in[6];
    const float* cb1    = (const float*)d_in[7];
    const float* cbn_s  = (const float*)d_in[8];
    const float* cbn_b  = (const float*)d_in[9];
    const float* cW2    = (const float*)d_in[10];
    const float* cb2    = (const float*)d_in[11];
    const float* bn_s   = (const float*)d_in[12];
    const float* bn_b   = (const float*)d_in[13];
    const float* vn0    = (const float*)d_in[14];
    const float* vW1    = (const float*)d_in[15];
    const float* vb1    = (const float*)d_in[16];
    const float* vbn1_s = (const float*)d_in[17];
    const float* vbn1_b = (const float*)d_in[18];
    const float* vW2    = (const float*)d_in[19];
    const float* vb2    = (const float*)d_in[20];
    const float* vbn2_s = (const float*)d_in[21];
    const float* vbn2_b = (const float*)d_in[22];
    const float* gW1    = (const float*)d_in[23];
    const float* gb1    = (const float*)d_in[24];
    const float* gbn_s  = (const float*)d_in[25];
    const float* gbn_b  = (const float*)d_in[26];
    const float* gW2    = (const float*)d_in[27];
    const float* gb2    = (const float*)d_in[28];
    const float* pW     = (const float*)d_in[29];
    const float* pb     = (const float*)d_in[30];

    float *H, *AGG, *HM, *T, *VN, *VT, *U;
    cudaGetSymbolAddress((void**)&H,   g_H);
    cudaGetSymbolAddress((void**)&AGG, g_AGG);
    cudaGetSymbolAddress((void**)&HM,  g_HMAX);
    cudaGetSymbolAddress((void**)&T,   g_T);
    cudaGetSymbolAddress((void**)&VN,  g_VN);
    cudaGetSymbolAddress((void**)&VT,  g_VTMP);
    cudaGetSymbolAddress((void**)&U,   g_U);

    detect_kernel<<<1, 1>>>(batch, eidx);
    init_vn_kernel<<<(GG*DD + 255)/256, 256>>>(vn0);

    // encoder: H = x @ enc_W + enc_b ; HMAX = H
    {
        dim3 g((NN + BM - 1)/BM, (DD + BN - 1)/BN);
        gemm_kernel<<<g, 256>>>(x, enc_W, enc_b, nullptr, nullptr,
                                H, HM, NN, DIN, DD, 0, 1);
    }

    for (int l = 0; l < LL; l++) {
        node_pre_kernel<<<(NN*32 + 255)/256, 256>>>(batch, eps, l, (l < LL-1) ? 1 : 0);
        edge_kernel<<<(int)(((long long)EE*32 + 255)/256), 256>>>(eidx);

        dim3 g1((NN + BM - 1)/BM, (2*DD + BN - 1)/BN);
        gemm_kernel<<<g1, 256>>>(AGG, cW1 + (size_t)l*DD*2*DD,
                                 cb1 + (size_t)l*2*DD, cbn_s + (size_t)l*2*DD, cbn_b + (size_t)l*2*DD,
                                 T, nullptr, NN, DD, 2*DD, 1, 0);
        dim3 g2((NN + BM - 1)/BM, (DD + BN - 1)/BN);
        gemm_kernel<<<g2, 256>>>(T, cW2 + (size_t)l*2*DD*DD,
                                 cb2 + (size_t)l*DD, bn_s + (size_t)l*DD, bn_b + (size_t)l*DD,
                                 H, HM, NN, 2*DD, DD, (l < LL-1) ? 1 : 0, 2);

        if (l < LL - 1) {
            dim3 v1((GG + BM - 1)/BM, (2*DD + BN - 1)/BN);
            gemm_kernel<<<v1, 256>>>(VT, vW1 + (size_t)l*DD*2*DD,
                                     vb1 + (size_t)l*2*DD, vbn1_s + (size_t)l*2*DD, vbn1_b + (size_t)l*2*DD,
                                     U, nullptr, GG, DD, 2*DD, 1, 0);
            dim3 v2((GG + BM - 1)/BM, (DD + BN - 1)/BN);
            gemm_kernel<<<v2, 256>>>(U, vW2 + (size_t)l*2*DD*DD,
                                     vb2 + (size_t)l*DD, vbn2_s + (size_t)l*DD, vbn2_b + (size_t)l*DD,
                                     VN, VT, GG, 2*DD, DD, 1, 1);  // copy into VTMP for next layer
        }
    }

    // gate MLP hidden: T = relu((HMAX @ gW1 + gb1)*gbn_s + gbn_b)
    {
        dim3 g((NN + BM - 1)/BM, (2*DD + BN - 1)/BN);
        gemm_kernel<<<g, 256>>>(HM, gW1, gb1, gbn_s, gbn_b, T, nullptr, NN, DD, 2*DD, 1, 0);
    }
    init_pool_kernel<<<(GG*DD + 255)/256, 256>>>();
    gate_kernel<<<(NN*32 + 255)/256, 256>>>(gW2, gb2, batch);
    exp_kernel<<<(NN + 255)/256, 256>>>(batch);
    pool_kernel<<<(NN*32 + 255)/256, 256>>>(batch);
    out_kernel<<<(GG*CC + 255)/256, 256>>>(pW, pb, (float*)d_out);
}

// round 3
// speedup vs baseline: 1.0513x; 1.0513x over previous
#include <cuda_runtime.h>
#include <cstdint>
#include <math.h>

// Problem constants (fixed by the reference)
#define NN 100000
#define EE 1600000
#define GG 1000
#define DIN 128
#define DD 300
#define LL 5
#define CC 10

// ---------------- persistent scratch ----------------
__device__ float g_H   [(size_t)NN*DD];
__device__ float g_HL  [(size_t)NN*DD];
__device__ float g_AGG [(size_t)NN*DD];
__device__ float g_HMAX[(size_t)NN*DD];
__device__ float g_T   [(size_t)NN*2*DD];
__device__ float g_VN  [(size_t)GG*DD];
__device__ float g_VTMP[(size_t)GG*DD];
__device__ float g_U   [(size_t)GG*2*DD];
__device__ float g_GATE[NN];
__device__ float g_E   [NN];
__device__ float g_GMAX[GG];
__device__ float g_ESUM[GG];
__device__ float g_GREP[(size_t)GG*DD];
__device__ int   g_is64_batch;
__device__ int   g_is64_edge;

// Pre-transposed + tf32-hi/lo-split weights: Bt[N][Kpad], Kpad = ceil32(K)
#define OFF_ENC 0
#define OFF_CW1 38400          /* + l*192000 (600x320) */
#define OFF_CW2 998400         /* + l*182400 (300x608) */
#define OFF_VW1 1910400
#define OFF_VW2 2870400
#define OFF_GW1 3782400        /* 600x320 */
#define BT_TOTAL 3974400
__device__ float g_BTH[BT_TOTAL];
__device__ float g_BTL[BT_TOTAL];

// ---------------- helpers ----------------
__device__ __forceinline__ float to_tf32(float x) {
    uint32_t u; asm("cvt.rna.tf32.f32 %0, %1;" : "=r"(u) : "f"(x));
    return __uint_as_float(u);
}
__device__ __forceinline__ void redAdd4(float4* p, float4 v) {
    asm volatile("red.global.add.v4.f32 [%0], {%1,%2,%3,%4};"
                 :: "l"(p), "f"(v.x), "f"(v.y), "f"(v.z), "f"(v.w) : "memory");
}
__device__ __forceinline__ long long ldidx(const void* p, long long i, int is64) {
    return is64 ? ((const long long*)p)[i] : (long long)((const int*)p)[i];
}
__device__ __forceinline__ void atomicMaxFloat(float* addr, float val) {
    int* ia = (int*)addr;
    int old = *ia;
    while (__int_as_float(old) < val) {
        int assumed = old;
        old = atomicCAS(ia, assumed, __float_as_int(val));
        if (old == assumed) break;
    }
}
// m16n8k8 tf32 tensor-core MMA (sm_80+ PTX; HMMA on SASS)
__device__ __forceinline__ void mma8(float4& d, const float* a, const float* b) {
    asm volatile(
        "mma.sync.aligned.m16n8k8.row.col.f32.tf32.tf32.f32 "
        "{%0,%1,%2,%3}, {%4,%5,%6,%7}, {%8,%9}, {%0,%1,%2,%3};"
        : "+f"(d.x), "+f"(d.y), "+f"(d.z), "+f"(d.w)
        : "r"(__float_as_uint(a[0])), "r"(__float_as_uint(a[1])),
          "r"(__float_as_uint(a[2])), "r"(__float_as_uint(a[3])),
          "r"(__float_as_uint(b[0])), "r"(__float_as_uint(b[1])));
}

__global__ void detect_kernel(const void* batch, const void* eidx) {
    const int* b = (const int*)batch;
    int z = 1;
    for (int i = 0; i < 64; i++) if (b[NN/2 + 2*i + 1] != 0) z = 0;
    g_is64_batch = z;
    const int* e = (const int*)eidx;
    int z2 = 1;
    for (int i = 0; i < 64; i++) if (e[2*i + 1] != 0) z2 = 0;
    g_is64_edge = z2;
}

// ---------------- weight transpose + tf32 hi/lo split ----------------
__global__ void split_weights_kernel(const float* __restrict__ enc, const float* __restrict__ cW1,
                                     const float* __restrict__ cW2, const float* __restrict__ vW1,
                                     const float* __restrict__ vW2, const float* __restrict__ gW1) {
    int job = blockIdx.y;
    const float* src; int K, N; size_t dst;
    if (job == 0)      { src = enc; K = 128; N = 300; dst = OFF_ENC; }
    else if (job < 6)  { int l = job - 1;  src = cW1 + (size_t)l*300*600; K = 300; N = 600; dst = OFF_CW1 + (size_t)l*192000; }
    else if (job < 11) { int l = job - 6;  src = cW2 + (size_t)l*600*300; K = 600; N = 300; dst = OFF_CW2 + (size_t)l*182400; }
    else if (job < 16) { int l = job - 11; src = vW1 + (size_t)l*300*600; K = 300; N = 600; dst = OFF_VW1 + (size_t)l*192000; }
    else if (job < 21) { int l = job - 16; src = vW2 + (size_t)l*600*300; K = 600; N = 300; dst = OFF_VW2 + (size_t)l*182400; }
    else               { src = gW1; K = 300; N = 600; dst = OFF_GW1; }
    int Kpad = ((K + 31) / 32) * 32;
    int tot = N * Kpad;
    int idx = blockIdx.x * blockDim.x + threadIdx.x;
    if (idx >= tot) return;
    int n = idx / Kpad, k = idx % Kpad;
    float v = (k < K) ? src[(size_t)k * N + n] : 0.0f;
    float h = to_tf32(v);
    float lo = to_tf32(v - h);
    g_BTH[dst + idx] = h;
    g_BTL[dst + idx] = lo;
}

// ---------------- tensor-core 3xTF32 GEMM (mma.sync m16n8k8) ----------------
// C[M,N] = epi(A[M,K] @ B[K,N]); Bt pre-split hi/lo [N][Kpad].
// CTA tile 128x128, 8 warps of 64x32, BK=16, double-buffered SMEM.
#define PITCH 20                      // floats per SMEM row (16 used + pad) -> conflict-free frags
#define MATF (128 * PITCH)            // floats per matrix buffer
#define STAGEF (4 * MATF)             // Ah, Al, Bh, Bl
#define GEMM_SMEM (2 * STAGEF * 4)    // bytes

__global__ void __launch_bounds__(256, 1)
gemm_mma(const float* __restrict__ A, const float* __restrict__ Bth, const float* __restrict__ Btl,
         const float* __restrict__ bias, const float* __restrict__ scale, const float* __restrict__ shift,
         float* __restrict__ C, float* __restrict__ EX,
         int M, int K, int Kpad, int N, int relu, int exmode)
{
    extern __shared__ float ds[];
    const int tid = threadIdx.x, warp = tid >> 5, lane = tid & 31;
    const int gid = lane >> 2, tig = lane & 3;
    const int wm = warp >> 2, wn = warp & 3;    // 2 x 4 warp grid
    const int m0 = blockIdx.x * 128;
    const int n0 = blockIdx.y * 128;

    float4 acc[4][4];
    #pragma unroll
    for (int i = 0; i < 4; i++)
        #pragma unroll
        for (int j = 0; j < 4; j++) acc[i][j] = make_float4(0.f, 0.f, 0.f, 0.f);

    const int nch = (K + 15) >> 4;

    auto load_chunk = [&](int s, int k0) {
        float* Ah = ds + s * STAGEF;
        float* Al = Ah + MATF;
        float* Bh = Al + MATF;
        float* Bl = Bh + MATF;
        #pragma unroll
        for (int i = 0; i < 2; i++) {
            int e = tid + i * 256;          // 512 float4 slots = 128 rows x 4 groups
            int row = e >> 2, c4 = (e & 3) * 4;
            // ---- A ----
            {
                int gr = m0 + row, gk = k0 + c4;
                float4 v = make_float4(0.f, 0.f, 0.f, 0.f);
                if (gr < M) {
                    int rem = K - gk;
                    if (rem >= 4) v = *(const float4*)(A + (size_t)gr * K + gk);
                    else {
                        const float* ap = A + (size_t)gr * K + gk;
                        if (rem > 0) v.x = ap[0];
                        if (rem > 1) v.y = ap[1];
                        if (rem > 2) v.z = ap[2];
                    }
                }
                float hx = to_tf32(v.x), hy = to_tf32(v.y), hz = to_tf32(v.z), hw = to_tf32(v.w);
                float* ah = Ah + row * PITCH + c4;
                float* al = Al + row * PITCH + c4;
                ah[0] = hx; ah[1] = hy; ah[2] = hz; ah[3] = hw;
                al[0] = to_tf32(v.x - hx); al[1] = to_tf32(v.y - hy);
                al[2] = to_tf32(v.z - hz); al[3] = to_tf32(v.w - hw);
            }
            // ---- B (pre-split, Kpad-padded) ----
            {
                int gn = n0 + row;
                float4 vh = make_float4(0.f, 0.f, 0.f, 0.f);
                float4 vl = make_float4(0.f, 0.f, 0.f, 0.f);
                if (gn < N) {
                    vh = *(const float4*)(Bth + (size_t)gn * Kpad + k0 + c4);
                    vl = *(const float4*)(Btl + (size_t)gn * Kpad + k0 + c4);
                }
                float* bh = Bh + row * PITCH + c4;
                float* bl = Bl + row * PITCH + c4;
                bh[0] = vh.x; bh[1] = vh.y; bh[2] = vh.z; bh[3] = vh.w;
                bl[0] = vl.x; bl[1] = vl.y; bl[2] = vl.z; bl[3] = vl.w;
            }
        }
    };

    load_chunk(0, 0);
    __syncthreads();

    for (int c = 0; c < nch; c++) {
        int s = c & 1;
        if (c + 1 < nch) load_chunk(s ^ 1, (c + 1) * 16);

        const float* Ah = ds + s * STAGEF;
        const float* Al = Ah + MATF;
        const float* Bh = Al + MATF;
        const float* Bl = Bh + MATF;

        #pragma unroll
        for (int kk = 0; kk < 16; kk += 8) {
            float ah[4][4], al[4][4], bh[4][2], bl[4][2];
            #pragma unroll
            for (int mt = 0; mt < 4; mt++) {
                int r = wm * 64 + mt * 16 + gid;
                const float* p0 = Ah + r * PITCH + kk + tig;
                const float* p1 = Ah + (r + 8) * PITCH + kk + tig;
                ah[mt][0] = p0[0]; ah[mt][1] = p1[0];
                ah[mt][2] = p0[4]; ah[mt][3] = p1[4];
                const float* q0 = Al + r * PITCH + kk + tig;
                const float* q1 = Al + (r + 8) * PITCH + kk + tig;
                al[mt][0] = q0[0]; al[mt][1] = q1[0];
                al[mt][2] = q0[4]; al[mt][3] = q1[4];
            }
            #pragma unroll
            for (int nt = 0; nt < 4; nt++) {
                int r = wn * 32 + nt * 8 + gid;
                const float* p = Bh + r * PITCH + kk + tig;
                bh[nt][0] = p[0]; bh[nt][1] = p[4];
                const float* q = Bl + r * PITCH + kk + tig;
                bl[nt][0] = q[0]; bl[nt][1] = q[4];
            }
            #pragma unroll
            for (int mt = 0; mt < 4; mt++)
                #pragma unroll
                for (int nt = 0; nt < 4; nt++) {
                    mma8(acc[mt][nt], al[mt], bh[nt]);
                    mma8(acc[mt][nt], ah[mt], bl[nt]);
                    mma8(acc[mt][nt], ah[mt], bh[nt]);
                }
        }
        __syncthreads();
    }

    // ---- epilogue ----
    #pragma unroll
    for (int mt = 0; mt < 4; mt++) {
        #pragma unroll
        for (int nt = 0; nt < 4; nt++) {
            int col = n0 + wn * 32 + nt * 8 + tig * 2;
            if (col >= N) continue;       // N even => col+1 < N too
            float2 bi = *(const float2*)(bias + col);
            float2 sc = make_float2(1.f, 1.f), sh = make_float2(0.f, 0.f);
            if (scale) {
                sc = *(const float2*)(scale + col);
                sh = *(const float2*)(shift + col);
            }
            #pragma unroll
            for (int h = 0; h < 2; h++) {
                int row = m0 + wm * 64 + mt * 16 + gid + h * 8;
                if (row >= M) continue;
                float y0 = h ? acc[mt][nt].z : acc[mt][nt].x;
                float y1 = h ? acc[mt][nt].w : acc[mt][nt].y;
                y0 = (y0 + bi.x) * sc.x + sh.x;
                y1 = (y1 + bi.y) * sc.y + sh.y;
                if (relu) { y0 = fmaxf(y0, 0.f); y1 = fmaxf(y1, 0.f); }
                float2* cp = (float2*)(C + (size_t)row * N + col);
                *cp = make_float2(y0, y1);
                if (exmode == 1) {
                    *(float2*)(EX + (size_t)row * N + col) = make_float2(y0, y1);
                } else if (exmode == 2) {
                    float2* e = (float2*)(EX + (size_t)row * N + col);
                    float2 o = *e;
                    e->x = fmaxf(o.x, y0);
                    e->y = fmaxf(o.y, y1);
                }
            }
        }
    }
}

// ---------------- per-node / per-edge kernels ----------------
__global__ void init_vn_kernel(const float* __restrict__ vn0) {
    int i = blockIdx.x * blockDim.x + threadIdx.x;
    if (i < GG * DD) {
        float v = vn0[i % DD];
        g_VN[i] = v;
        g_VTMP[i] = v;
    }
}

__global__ void node_pre_kernel(const void* __restrict__ batch,
                                const float* __restrict__ eps, int l, int addVT) {
    int w = (blockIdx.x * blockDim.x + threadIdx.x) >> 5;
    int lane = threadIdx.x & 31;
    if (w >= NN) return;
    int is64 = g_is64_batch;
    long long b = ldidx(batch, w, is64);
    float e1 = 1.0f + __ldg(eps + l);
    const float4* h  = (const float4*)(g_H  + (size_t)w * DD);
    const float4* vn = (const float4*)(g_VN + (size_t)b * DD);
    float4* hl = (float4*)(g_HL  + (size_t)w * DD);
    float4* ag = (float4*)(g_AGG + (size_t)w * DD);
    float4* vt = (float4*)(g_VTMP + (size_t)b * DD);
    for (int c = lane; c < DD/4; c += 32) {
        float4 hv = h[c], vv = vn[c];
        float4 s = make_float4(hv.x+vv.x, hv.y+vv.y, hv.z+vv.z, hv.w+vv.w);
        hl[c] = s;
        ag[c] = make_float4(s.x*e1, s.y*e1, s.z*e1, s.w*e1);
        if (addVT) redAdd4(vt + c, s);
    }
}

__global__ void edge_kernel(const void* __restrict__ ei) {
    long long w = ((long long)blockIdx.x * blockDim.x + threadIdx.x) >> 5;
    int lane = threadIdx.x & 31;
    if (w >= EE) return;
    int is64 = g_is64_edge;
    long long s = ldidx(ei, w, is64);
    long long d = ldidx(ei, (long long)EE + w, is64);
    const float4* src = (const float4*)(g_HL + (size_t)s * DD);
    float4* dst = (float4*)(g_AGG + (size_t)d * DD);
    #pragma unroll
    for (int c = lane; c < DD/4; c += 32)
        redAdd4(dst + c, __ldg(src + c));
}

__global__ void init_pool_kernel() {
    int i = blockIdx.x * blockDim.x + threadIdx.x;
    if (i < GG) { g_GMAX[i] = __int_as_float(0xff800000); g_ESUM[i] = 0.f; }
    if (i < GG * DD) g_GREP[i] = 0.f;
}

__global__ void gate_kernel(const float* __restrict__ gW2, const float* __restrict__ gb2,
                            const void* __restrict__ batch) {
    int w = (blockIdx.x * blockDim.x + threadIdx.x) >> 5;
    int lane = threadIdx.x & 31;
    if (w >= NN) return;
    const float* t = g_T + (size_t)w * (2*DD);
    float s = 0.f;
    for (int c = lane; c < 2*DD; c += 32) s += t[c] * __ldg(gW2 + c);
    #pragma unroll
    for (int o = 16; o > 0; o >>= 1) s += __shfl_xor_sync(0xffffffffu, s, o);
    if (lane == 0) {
        float g = s + __ldg(gb2);
        g_GATE[w] = g;
        long long b = ldidx(batch, w, g_is64_batch);
        atomicMaxFloat(&g_GMAX[b], g);
    }
}

__global__ void exp_kernel(const void* __restrict__ batch) {
    int i = blockIdx.x * blockDim.x + threadIdx.x;
    if (i >= NN) return;
    long long b = ldidx(batch, i, g_is64_batch);
    float e = expf(g_GATE[i] - g_GMAX[b]);
    g_E[i] = e;
    atomicAdd(&g_ESUM[b], e);
}

__global__ void pool_kernel(const void* __restrict__ batch) {
    int w = (blockIdx.x * blockDim.x + threadIdx.x) >> 5;
    int lane = threadIdx.x & 31;
    if (w >= NN) return;
    long long b = ldidx(batch, w, g_is64_batch);
    float wgt = g_E[w] / g_ESUM[b];
    const float4* src = (const float4*)(g_HMAX + (size_t)w * DD);
    float4* dst = (float4*)(g_GREP + (size_t)b * DD);
    #pragma unroll
    for (int c = lane; c < DD/4; c += 32) {
        float4 v = src[c];
        redAdd4(dst + c, make_float4(v.x*wgt, v.y*wgt, v.z*wgt, v.w*wgt));
    }
}

__global__ void out_kernel(const float* __restrict__ pW, const float* __restrict__ pb,
                           float* __restrict__ out) {
    int i = blockIdx.x * blockDim.x + threadIdx.x;
    if (i >= GG * CC) return;
    int g = i / CC, c = i % CC;
    float s = __ldg(pb + c);
    const float* gr = g_GREP + (size_t)g * DD;
    for (int k = 0; k < DD; k++) s += gr[k] * __ldg(pW + k * CC + c);
    out[i] = s;
}

// ---------------- host-side GEMM dispatcher ----------------
static void launch_gemm(const float* A, const float* bth, const float* btl,
                        const float* bias, const float* scale, const float* shift,
                        float* C, float* EX, int M, int K, int N, int relu, int exmode) {
    int Kpad = ((K + 31) / 32) * 32;
    dim3 g((M + 127) / 128, (N + 127) / 128);
    gemm_mma<<<g, 256, GEMM_SMEM>>>(A, bth, btl, bias, scale, shift, C, EX,
                                    M, K, Kpad, N, relu, exmode);
}

// ---------------- launch ----------------
extern "C" void kernel_launch(void* const* d_in, const int* in_sizes, int n_in,
                              void* d_out, int out_size) {
    const float* x      = (const float*)d_in[0];
    const void*  eidx   = d_in[1];
    const void*  batch  = d_in[2];
    const float* enc_W  = (const float*)d_in[3];
    const float* enc_b  = (const float*)d_in[4];
    const float* eps    = (const float*)d_in[5];
    const float* cW1    = (const float*)d_in[6];
    const float* cb1    = (const float*)d_in[7];
    const float* cbn_s  = (const float*)d_in[8];
    const float* cbn_b  = (const float*)d_in[9];
    const float* cW2    = (const float*)d_in[10];
    const float* cb2    = (const float*)d_in[11];
    const float* bn_s   = (const float*)d_in[12];
    const float* bn_b   = (const float*)d_in[13];
    const float* vn0    = (const float*)d_in[14];
    const float* vW1    = (const float*)d_in[15];
    const float* vb1    = (const float*)d_in[16];
    const float* vbn1_s = (const float*)d_in[17];
    const float* vbn1_b = (const float*)d_in[18];
    const float* vW2    = (const float*)d_in[19];
    const float* vb2    = (const float*)d_in[20];
    const float* vbn2_s = (const float*)d_in[21];
    const float* vbn2_b = (const float*)d_in[22];
    const float* gW1    = (const float*)d_in[23];
    const float* gb1    = (const float*)d_in[24];
    const float* gbn_s  = (const float*)d_in[25];
    const float* gbn_b  = (const float*)d_in[26];
    const float* gW2    = (const float*)d_in[27];
    const float* gb2    = (const float*)d_in[28];
    const float* pW     = (const float*)d_in[29];
    const float* pb     = (const float*)d_in[30];

    static bool attr_done = false;
    if (!attr_done) {
        cudaFuncSetAttribute(gemm_mma, cudaFuncAttributeMaxDynamicSharedMemorySize, GEMM_SMEM);
        attr_done = true;
    }

    float *H, *AGG, *HM, *T, *VN, *VT, *U, *BTH, *BTL;
    cudaGetSymbolAddress((void**)&H,   g_H);
    cudaGetSymbolAddress((void**)&AGG, g_AGG);
    cudaGetSymbolAddress((void**)&HM,  g_HMAX);
    cudaGetSymbolAddress((void**)&T,   g_T);
    cudaGetSymbolAddress((void**)&VN,  g_VN);
    cudaGetSymbolAddress((void**)&VT,  g_VTMP);
    cudaGetSymbolAddress((void**)&U,   g_U);
    cudaGetSymbolAddress((void**)&BTH, g_BTH);
    cudaGetSymbolAddress((void**)&BTL, g_BTL);

    detect_kernel<<<1, 1>>>(batch, eidx);
    split_weights_kernel<<<dim3(750, 22), 256>>>(enc_W, cW1, cW2, vW1, vW2, gW1);
    init_vn_kernel<<<(GG*DD + 255)/256, 256>>>(vn0);

    // encoder: H = x @ enc_W + enc_b ; HMAX = H
    launch_gemm(x, BTH + OFF_ENC, BTL + OFF_ENC, enc_b, nullptr, nullptr,
                H, HM, NN, DIN, DD, 0, 1);

    for (int l = 0; l < LL; l++) {
        node_pre_kernel<<<(NN*32 + 255)/256, 256>>>(batch, eps, l, (l < LL-1) ? 1 : 0);
        edge_kernel<<<(int)(((long long)EE*32 + 255)/256), 256>>>(eidx);

        launch_gemm(AGG, BTH + OFF_CW1 + (size_t)l*192000, BTL + OFF_CW1 + (size_t)l*192000,
                    cb1 + (size_t)l*2*DD, cbn_s + (size_t)l*2*DD, cbn_b + (size_t)l*2*DD,
                    T, nullptr, NN, DD, 2*DD, 1, 0);
        launch_gemm(T, BTH + OFF_CW2 + (size_t)l*182400, BTL + OFF_CW2 + (size_t)l*182400,
                    cb2 + (size_t)l*DD, bn_s + (size_t)l*DD, bn_b + (size_t)l*DD,
                    H, HM, NN, 2*DD, DD, (l < LL-1) ? 1 : 0, 2);

        if (l < LL - 1) {
            launch_gemm(VT, BTH + OFF_VW1 + (size_t)l*192000, BTL + OFF_VW1 + (size_t)l*192000,
                        vb1 + (size_t)l*2*DD, vbn1_s + (size_t)l*2*DD, vbn1_b + (size_t)l*2*DD,
                        U, nullptr, GG, DD, 2*DD, 1, 0);
            launch_gemm(U, BTH + OFF_VW2 + (size_t)l*182400, BTL + OFF_VW2 + (size_t)l*182400,
                        vb2 + (size_t)l*DD, vbn2_s + (size_t)l*DD, vbn2_b + (size_t)l*DD,
                        VN, VT, GG, 2*DD, DD, 1, 1);
        }
    }

    launch_gemm(HM, BTH + OFF_GW1, BTL + OFF_GW1, gb1, gbn_s, gbn_b,
                T, nullptr, NN, DD, 2*DD, 1, 0);
    init_pool_kernel<<<(GG*DD + 255)/256, 256>>>();
    gate_kernel<<<(NN*32 + 255)/256, 256>>>(gW2, gb2, batch);
    exp_kernel<<<(NN + 255)/256, 256>>>(batch);
    pool_kernel<<<(NN*32 + 255)/256, 256>>>(batch);
    out_kernel<<<(GG*CC + 255)/256, 256>>>(pW, pb, (float*)d_out);
}